// round 1
// baseline (speedup 1.0000x reference)
#include <cuda_runtime.h>

#define MATOMS 8192
#define NGRAPH 16
#define NATOM  512
#define FDIM 128
#define HDIM 64
#define DDIM 16
#define SEIN 95
#define EHIN 159
#define LUTN 8192
#define LUT_MAX 160.0f

__device__ float g_src[MATOMS * DDIM];
__device__ float g_shell[MATOMS * SEIN];
__device__ float g_lut[LUTN + 1];
__device__ float g_pa[MATOMS];

__device__ __forceinline__ float wred(float v) {
#pragma unroll
    for (int o = 16; o; o >>= 1) v += __shfl_xor_sync(0xffffffffu, v, o);
    return v;
}
__device__ __forceinline__ float siluf(float z) { return z / (1.f + expf(-z)); }

// ---------------------------------------------------------------------------
// 1. Kernel LUT: ker(d) = base(d) * gate(d) is a pure function of d.
//    Evaluate exactly at LUTN+1 nodes over [0, LUT_MAX]; pairwise kernel
//    linearly interpolates. Only d >= 5 is ever used (shell masks).
// ---------------------------------------------------------------------------
__global__ void lut_kernel(const float* ks_p, const float* w1, const float* b1,
                           const float* w2, const float* b2) {
    int k = blockIdx.x * blockDim.x + threadIdx.x;
    if (k > LUTN) return;
    float d = (float)k * (LUT_MAX / (float)LUTN);
    float screening = log1pf(expf(*ks_p));
    float base = expf(-screening * d) / fmaxf(d, 1e-6f);
    float gin[10];
    gin[0] = d * (1.f / 5.f);
    gin[1] = d * (1.f / 40.f);
#pragma unroll
    for (int r = 0; r < 8; r++) {
        float c = 5.f + 5.f * (float)r;  // linspace(5, 40, 8)
        float t = d - c;
        gin[2 + r] = expf(-t * t * (1.f / 25.f));  // gamma = 1/spacing^2 = 1/25
    }
    float out = b2[0];
    for (int j = 0; j < 32; j++) {
        float z = b1[j];
#pragma unroll
        for (int i = 0; i < 10; i++) z = fmaf(gin[i], w1[i * 32 + j], z);
        out = fmaf(siluf(z), w2[j], out);
    }
    g_lut[k] = base * (1.f + tanhf(out));
}

// ---------------------------------------------------------------------------
// 2. Per-atom source features: LN(x[128]) -> 64 (silu) -> 16 -> LN
//    Warp per atom, weights staged in shared.
// ---------------------------------------------------------------------------
__global__ void __launch_bounds__(256) src_kernel(
    const float* __restrict__ x, const float* __restrict__ w1, const float* __restrict__ b1,
    const float* __restrict__ w2, const float* __restrict__ b2,
    const float* __restrict__ lng, const float* __restrict__ lnb,
    const float* __restrict__ slng, const float* __restrict__ slnb) {
    __shared__ float sW1[FDIM * HDIM];
    __shared__ float sW2[HDIM * DDIM];
    __shared__ float sB1[HDIM], sB2[DDIM];
    __shared__ float sLnG[FDIM], sLnB[FDIM], sSLnG[DDIM], sSLnB[DDIM];
    __shared__ float xnB[8][FDIM];
    __shared__ float hB[8][HDIM];
    int tid = threadIdx.x;
    for (int i = tid; i < FDIM * HDIM; i += 256) sW1[i] = w1[i];
    for (int i = tid; i < HDIM * DDIM; i += 256) sW2[i] = w2[i];
    if (tid < HDIM) sB1[tid] = b1[tid];
    if (tid < DDIM) sB2[tid] = b2[tid];
    if (tid < FDIM) { sLnG[tid] = lng[tid]; sLnB[tid] = lnb[tid]; }
    if (tid < DDIM) { sSLnG[tid] = slng[tid]; sSLnB[tid] = slnb[tid]; }
    __syncthreads();
    int w = tid >> 5, lane = tid & 31;
    for (int t = 0; t < 4; t++) {
        int a = blockIdx.x * 32 + w * 4 + t;
        float4 v = ((const float4*)(x + a * FDIM))[lane];
        float s = wred(v.x + v.y + v.z + v.w);
        float m = s * (1.f / 128.f);
        float d0 = v.x - m, d1 = v.y - m, d2 = v.z - m, d3 = v.w - m;
        float ss = wred(d0 * d0 + d1 * d1 + d2 * d2 + d3 * d3);
        float rstd = rsqrtf(ss * (1.f / 128.f) + 1e-5f);
        int k0 = lane * 4;
        xnB[w][k0 + 0] = fmaf(d0 * rstd, sLnG[k0 + 0], sLnB[k0 + 0]);
        xnB[w][k0 + 1] = fmaf(d1 * rstd, sLnG[k0 + 1], sLnB[k0 + 1]);
        xnB[w][k0 + 2] = fmaf(d2 * rstd, sLnG[k0 + 2], sLnB[k0 + 2]);
        xnB[w][k0 + 3] = fmaf(d3 * rstd, sLnG[k0 + 3], sLnB[k0 + 3]);
        __syncwarp();
        float h0 = sB1[lane], h1 = sB1[lane + 32];
        for (int k = 0; k < FDIM; k++) {
            float xv = xnB[w][k];
            h0 = fmaf(xv, sW1[k * 64 + lane], h0);
            h1 = fmaf(xv, sW1[k * 64 + lane + 32], h1);
        }
        hB[w][lane] = siluf(h0);
        hB[w][lane + 32] = siluf(h1);
        __syncwarp();
        float oc = 0.f;
        if (lane < 16) {
            oc = sB2[lane];
            for (int k = 0; k < HDIM; k++) oc = fmaf(hB[w][k], sW2[k * 16 + lane], oc);
        }
        // LN over 16 (lanes 0..15 exchange among themselves for offsets <= 8)
        float s2 = oc;
#pragma unroll
        for (int o = 8; o; o >>= 1) s2 += __shfl_xor_sync(0xffffffffu, s2, o);
        float mm = s2 * (1.f / 16.f);
        float dv = oc - mm;
        float vs = dv * dv;
#pragma unroll
        for (int o = 8; o; o >>= 1) vs += __shfl_xor_sync(0xffffffffu, vs, o);
        float rs = rsqrtf(vs * (1.f / 16.f) + 1e-5f);
        if (lane < 16) g_src[a * DDIM + lane] = fmaf(dv * rs, sSLnG[lane], sSLnB[lane]);
        __syncwarp();
    }
}

// ---------------------------------------------------------------------------
// 3. Graph-wise neutralization: subtract per-graph mean of src (cnt = 512)
// ---------------------------------------------------------------------------
__global__ void center_kernel() {
    int g = blockIdx.x;
    __shared__ float part[256];
    __shared__ float mean[DDIM];
    int tid = threadIdx.x;
    int c = tid & 15, p = tid >> 4;
    float s = 0.f;
    for (int j = p; j < NATOM; j += 16) s += g_src[(g * NATOM + j) * DDIM + c];
    part[tid] = s;
    __syncthreads();
    if (tid < DDIM) {
        float t = 0.f;
        for (int q = 0; q < 16; q++) t += part[q * 16 + tid];
        mean[tid] = t * (1.f / (float)NATOM);
    }
    __syncthreads();
    for (int idx = tid; idx < NATOM * DDIM; idx += 256)
        g_src[g * NATOM * DDIM + idx] -= mean[idx & 15];
}

// ---------------------------------------------------------------------------
// 4. Pairwise shell statistics. Block = (graph, 8-atom tile); warp per atom i.
// ---------------------------------------------------------------------------
template <int Q>
__device__ __forceinline__ void acc_shell(float (&aM)[5][16], float (&aC)[5], float (&aR)[5],
                                          float (&aR2)[5], float ker, float d,
                                          const float (&sj)[16]) {
    aC[Q] += 1.f;
    aR[Q] += d;
    aR2[Q] += d * d;
#pragma unroll
    for (int c = 0; c < 16; c++) aM[Q][c] = fmaf(ker, sj[c], aM[Q][c]);
}

__global__ void __launch_bounds__(256) pair_kernel(const float* __restrict__ pos) {
    __shared__ float sX[NATOM], sY[NATOM], sZ[NATOM];
    __shared__ float sS[16][NATOM + 8];
    int g = blockIdx.x >> 6;
    int tid = threadIdx.x;
    const float* pg = pos + g * NATOM * 3;
    for (int j = tid; j < NATOM; j += 256) {
        sX[j] = pg[j * 3 + 0];
        sY[j] = pg[j * 3 + 1];
        sZ[j] = pg[j * 3 + 2];
    }
    const float* sg = g_src + g * NATOM * DDIM;
    for (int idx = tid; idx < NATOM * 4; idx += 256) {
        int j = idx >> 2, c4 = (idx & 3) * 4;
        float4 v = *(const float4*)(sg + j * 16 + c4);
        sS[c4 + 0][j] = v.x;
        sS[c4 + 1][j] = v.y;
        sS[c4 + 2][j] = v.z;
        sS[c4 + 3][j] = v.w;
    }
    __syncthreads();
    int w = tid >> 5, lane = tid & 31;
    int il = (blockIdx.x & 63) * 8 + w;
    float px = sX[il], py = sY[il], pz = sZ[il];
    float accM[5][16], accC[5], accR[5], accR2[5];
#pragma unroll
    for (int q = 0; q < 5; q++) {
        accC[q] = 0.f; accR[q] = 0.f; accR2[q] = 0.f;
#pragma unroll
        for (int c = 0; c < 16; c++) accM[q][c] = 0.f;
    }
    const float inv_step = (float)LUTN / LUT_MAX;
    for (int j = lane; j < NATOM; j += 32) {
        float dx = px - sX[j], dy = py - sY[j], dz = pz - sZ[j];
        float d2 = fmaf(dx, dx, fmaf(dy, dy, dz * dz)) + 1e-12f;
        float d = sqrtf(d2);
        if (d < 5.f) continue;  // also excludes self (d = 1e-6)
        float fi = d * inv_step;
        int k = (int)fi;
        if (k > LUTN - 1) k = LUTN - 1;
        float fr = fi - (float)k;
        float v0 = __ldg(&g_lut[k]), v1 = __ldg(&g_lut[k + 1]);
        float ker = fmaf(v1 - v0, fr, v0);
        float sj[16];
#pragma unroll
        for (int c = 0; c < 16; c++) sj[c] = sS[c][j];
        if (d < 10.f)      acc_shell<0>(accM, accC, accR, accR2, ker, d, sj);
        else if (d < 20.f) acc_shell<1>(accM, accC, accR, accR2, ker, d, sj);
        else if (d < 40.f) acc_shell<2>(accM, accC, accR, accR2, ker, d, sj);
        else if (d < 80.f) acc_shell<3>(accM, accC, accR, accR2, ker, d, sj);
        else               acc_shell<4>(accM, accC, accR, accR2, ker, d, sj);
    }
#pragma unroll
    for (int q = 0; q < 5; q++) {
        accC[q] = wred(accC[q]);
        accR[q] = wred(accR[q]);
        accR2[q] = wred(accR2[q]);
#pragma unroll
        for (int c = 0; c < 16; c++) accM[q][c] = wred(accM[q][c]);
    }
    if (lane == 0) {
        float* outp = g_shell + (g * NATOM + il) * SEIN;
#pragma unroll
        for (int q = 0; q < 5; q++) {
            float inv = 1.f / fmaxf(accC[q], 1.f);
#pragma unroll
            for (int c = 0; c < 16; c++) outp[q * 19 + c] = accM[q][c] * inv;
            outp[q * 19 + 16] = accC[q];
            outp[q * 19 + 17] = accR[q] * inv;
            outp[q * 19 + 18] = sqrtf(accR2[q] * inv + 1e-12f);
        }
    }
}

// ---------------------------------------------------------------------------
// 5. Head: LN(shell) -> se MLP -> emb; ein[159]; LN -> eh MLP -> pa
// ---------------------------------------------------------------------------
#define HEAD_SMEM_FLOATS (6080 + 64 + 1024 + 16 + 10176 + 64 + 64 + 16 + 96 + 96 + 160 + 160 + 1280 + 512)
#define HEAD_SMEM (HEAD_SMEM_FLOATS * 4)

__global__ void __launch_bounds__(256) head_kernel(
    const float* __restrict__ seLnG_, const float* __restrict__ seLnB_,
    const float* __restrict__ seW1_, const float* __restrict__ seB1_,
    const float* __restrict__ seW2_, const float* __restrict__ seB2_,
    const float* __restrict__ ehLnG_, const float* __restrict__ ehLnB_,
    const float* __restrict__ ehW1_, const float* __restrict__ ehB1_,
    const float* __restrict__ ehW2_, const float* __restrict__ ehB2_,
    const float* __restrict__ far_gate, const float* __restrict__ energy_scale) {
    extern __shared__ float sm[];
    float* seW1 = sm;                 // 95*64 = 6080
    float* seB1 = seW1 + 6080;        // 64
    float* seW2 = seB1 + 64;          // 64*16 = 1024
    float* seB2 = seW2 + 1024;        // 16
    float* ehW1 = seB2 + 16;          // 159*64 = 10176
    float* ehB1 = ehW1 + 10176;       // 64
    float* ehW2 = ehB1 + 64;          // 64
    float* ehB2s = ehW2 + 64;         // 16 (pad)
    float* seLnG = ehB2s + 16;        // 96
    float* seLnB = seLnG + 96;        // 96
    float* ehLnG = seLnB + 96;        // 160
    float* ehLnB = ehLnG + 160;       // 160
    float* zALL = ehLnB + 160;        // 8*160
    float* hALL = zALL + 1280;        // 8*64
    int tid = threadIdx.x;
    for (int i = tid; i < 6080; i += 256) seW1[i] = seW1_[i];
    for (int i = tid; i < 1024; i += 256) seW2[i] = seW2_[i];
    for (int i = tid; i < 10176; i += 256) ehW1[i] = ehW1_[i];
    if (tid < 64) { seB1[tid] = seB1_[tid]; ehB1[tid] = ehB1_[tid]; ehW2[tid] = ehW2_[tid]; }
    if (tid < 16) seB2[tid] = seB2_[tid];
    if (tid == 0) ehB2s[0] = ehB2_[0];
    if (tid < 95) { seLnG[tid] = seLnG_[tid]; seLnB[tid] = seLnB_[tid]; }
    if (tid < 159) { ehLnG[tid] = ehLnG_[tid]; ehLnB[tid] = ehLnB_[tid]; }
    __syncthreads();
    int w = tid >> 5, lane = tid & 31;
    float* z = zALL + w * 160;
    float* h = hALL + w * 64;
    float scale = tanhf(*far_gate) * expf(*energy_scale);
    for (int t = 0; t < 4; t++) {
        int a = blockIdx.x * 32 + w * 4 + t;
        const float* shp = g_shell + a * SEIN;
        float v0 = shp[lane];
        float v1 = shp[lane + 32];
        float v2 = (lane < 31) ? shp[lane + 64] : 0.f;
        float s = wred(v0 + v1 + v2);
        float m = s * (1.f / 95.f);
        float e0 = v0 - m, e1 = v1 - m, e2 = (lane < 31) ? (v2 - m) : 0.f;
        float ss = wred(e0 * e0 + e1 * e1 + e2 * e2);
        float rstd = rsqrtf(ss * (1.f / 95.f) + 1e-5f);
        z[lane] = fmaf(e0 * rstd, seLnG[lane], seLnB[lane]);
        z[lane + 32] = fmaf(e1 * rstd, seLnG[lane + 32], seLnB[lane + 32]);
        if (lane < 31) z[lane + 64] = fmaf(e2 * rstd, seLnG[lane + 64], seLnB[lane + 64]);
        __syncwarp();
        float h0 = seB1[lane], h1 = seB1[lane + 32];
        for (int k = 0; k < 95; k++) {
            float zv = z[k];
            h0 = fmaf(zv, seW1[k * 64 + lane], h0);
            h1 = fmaf(zv, seW1[k * 64 + lane + 32], h1);
        }
        h[lane] = siluf(h0);
        h[lane + 32] = siluf(h1);
        __syncwarp();
        float srcc = 0.f, embc = 0.f;
        if (lane < 16) {
            embc = seB2[lane];
            for (int k = 0; k < 64; k++) embc = fmaf(h[k], seW2[k * 16 + lane], embc);
            srcc = g_src[a * DDIM + lane];
        }
        __syncwarp();
        if (lane < 16) {
            z[lane] = srcc;
            z[16 + lane] = embc;
            z[32 + lane] = srcc * embc;
            z[48 + lane] = srcc - embc;
        }
        z[64 + lane] = v0;
        z[96 + lane] = v1;
        if (lane < 31) z[128 + lane] = v2;
        __syncwarp();
        float a0 = z[lane], a1 = z[lane + 32], a2 = z[lane + 64], a3 = z[lane + 96];
        float a4 = (lane < 31) ? z[lane + 128] : 0.f;
        float s2 = wred(a0 + a1 + a2 + a3 + a4);
        float m2 = s2 * (1.f / 159.f);
        float q0 = a0 - m2, q1 = a1 - m2, q2 = a2 - m2, q3 = a3 - m2;
        float q4 = (lane < 31) ? (a4 - m2) : 0.f;
        float ss2 = wred(q0 * q0 + q1 * q1 + q2 * q2 + q3 * q3 + q4 * q4);
        float rstd2 = rsqrtf(ss2 * (1.f / 159.f) + 1e-5f);
        z[lane] = fmaf(q0 * rstd2, ehLnG[lane], ehLnB[lane]);
        z[lane + 32] = fmaf(q1 * rstd2, ehLnG[lane + 32], ehLnB[lane + 32]);
        z[lane + 64] = fmaf(q2 * rstd2, ehLnG[lane + 64], ehLnB[lane + 64]);
        z[lane + 96] = fmaf(q3 * rstd2, ehLnG[lane + 96], ehLnB[lane + 96]);
        if (lane < 31) z[lane + 128] = fmaf(q4 * rstd2, ehLnG[lane + 128], ehLnB[lane + 128]);
        __syncwarp();
        float g0 = ehB1[lane], g1 = ehB1[lane + 32];
        for (int k = 0; k < 159; k++) {
            float zv = z[k];
            g0 = fmaf(zv, ehW1[k * 64 + lane], g0);
            g1 = fmaf(zv, ehW1[k * 64 + lane + 32], g1);
        }
        g0 = siluf(g0);
        g1 = siluf(g1);
        float p = wred(g0 * ehW2[lane] + g1 * ehW2[lane + 32]);
        if (lane == 0) g_pa[a] = (p + ehB2s[0]) * scale;
        __syncwarp();
    }
}

// ---------------------------------------------------------------------------
// 6. Deterministic per-graph reduction
// ---------------------------------------------------------------------------
__global__ void reduce_kernel(float* __restrict__ out) {
    int g = blockIdx.x, tid = threadIdx.x;
    __shared__ float buf[256];
    float s = 0.f;
    for (int j = tid; j < NATOM; j += 256) s += g_pa[g * NATOM + j];
    buf[tid] = s;
    __syncthreads();
    for (int o = 128; o; o >>= 1) {
        if (tid < o) buf[tid] += buf[tid + o];
        __syncthreads();
    }
    if (tid == 0) out[g] = buf[0];
}

extern "C" void kernel_launch(void* const* d_in, const int* in_sizes, int n_in,
                              void* d_out, int out_size) {
    const float* x = (const float*)d_in[0];
    const float* pos = (const float*)d_in[1];
    // d_in[2] = batch, d_in[3] = num_graphs: layout is fixed (16 graphs x 512 atoms)
    const float* in_ln_g = (const float*)d_in[4];
    const float* in_ln_b = (const float*)d_in[5];
    const float* src_w1 = (const float*)d_in[6];
    const float* src_b1 = (const float*)d_in[7];
    const float* src_w2 = (const float*)d_in[8];
    const float* src_b2 = (const float*)d_in[9];
    const float* src_ln_g = (const float*)d_in[10];
    const float* src_ln_b = (const float*)d_in[11];
    const float* se_ln_g = (const float*)d_in[12];
    const float* se_ln_b = (const float*)d_in[13];
    const float* se_w1 = (const float*)d_in[14];
    const float* se_b1 = (const float*)d_in[15];
    const float* se_w2 = (const float*)d_in[16];
    const float* se_b2 = (const float*)d_in[17];
    const float* eh_ln_g = (const float*)d_in[18];
    const float* eh_ln_b = (const float*)d_in[19];
    const float* eh_w1 = (const float*)d_in[20];
    const float* eh_b1 = (const float*)d_in[21];
    const float* eh_w2 = (const float*)d_in[22];
    const float* eh_b2 = (const float*)d_in[23];
    const float* k_screen = (const float*)d_in[24];
    const float* kg_w1 = (const float*)d_in[25];
    const float* kg_b1 = (const float*)d_in[26];
    const float* kg_w2 = (const float*)d_in[27];
    const float* kg_b2 = (const float*)d_in[28];
    const float* far_gate = (const float*)d_in[29];
    const float* energy_scale = (const float*)d_in[30];
    float* out = (float*)d_out;

    cudaFuncSetAttribute(head_kernel, cudaFuncAttributeMaxDynamicSharedMemorySize, HEAD_SMEM);

    lut_kernel<<<(LUTN + 1 + 255) / 256, 256>>>(k_screen, kg_w1, kg_b1, kg_w2, kg_b2);
    src_kernel<<<MATOMS / 32, 256>>>(x, src_w1, src_b1, src_w2, src_b2,
                                     in_ln_g, in_ln_b, src_ln_g, src_ln_b);
    center_kernel<<<NGRAPH, 256>>>();
    pair_kernel<<<NGRAPH * 64, 256>>>(pos);
    head_kernel<<<MATOMS / 32, 256, HEAD_SMEM>>>(se_ln_g, se_ln_b, se_w1, se_b1, se_w2, se_b2,
                                                 eh_ln_g, eh_ln_b, eh_w1, eh_b1, eh_w2, eh_b2,
                                                 far_gate, energy_scale);
    reduce_kernel<<<NGRAPH, 256>>>(out);
}